// round 7
// baseline (speedup 1.0000x reference)
#include <cuda_runtime.h>

// TritonDualLIF: x [T=16,B=32,N=196,C=512] f32, decay scalar.
// v = d*v + x[t]; vpool[t,b,c] = mean_n(pre-reset v); s = (v>=1); v = s?0:v.
// out = spikes [T,B,N,C] ++ vpool [T,B,C].
//
// float4 lanes, N split into 7 chunks of 28 rows -> 896 CTAs (~6/SM, one
// wave at launch_bounds(256,6)). Pool partials flushed to scratch every 4
// timesteps (16KB smem). Last-arriving CTA of each 7-chunk group combines.

#define T_ 16
#define B_ 32
#define N_ 196
#define C_ 512
#define C4 (C_ / 4)        // 128 float4 per row
#define NH 7
#define NSUB 28            // 196/7
#define NLANES 8
#define JMAX 4             // ty<4 -> 4 iters, ty>=4 -> 3  (4*4+4*3=28)
#define NGROUP 128         // B_ * (C4/32) = 32*4

// Per-chunk partial sums: [NH][group][T*32] float4 = 7.3 MB scratch.
__device__ float4   g_part[NH * NGROUP * T_ * 32];
__device__ unsigned g_ctr[NGROUP];   // mod-7 last-arrival election (replay safe)

__global__ __launch_bounds__(256, 6)
void lif_dual_kernel(const float4* __restrict__ x,
                     const float* __restrict__ decay,
                     float* __restrict__ out) {
    const int tx   = threadIdx.x;     // c4 lane 0..31
    const int ty   = threadIdx.y;     // n lane 0..7
    const int cblk = blockIdx.x;      // 0..3
    const int b    = blockIdx.y;      // 0..31
    const int z    = blockIdx.z;      // 0..6  (N chunk)
    const float d  = decay[0];

    float4* __restrict__ spikes = (float4*)out;
    float4* __restrict__ vpool  = (float4*)(out + (size_t)T_ * B_ * N_ * C_);

    __shared__ float4 red[NLANES][4][32];   // 16 KB: 4-timestep window
    __shared__ int    s_last;

    float4 v[JMAX];
#pragma unroll
    for (int j = 0; j < JMAX; ++j) v[j] = make_float4(0.f, 0.f, 0.f, 0.f);

    const unsigned c4      = (unsigned)cblk * 32u + (unsigned)tx;
    const unsigned bbase   = (unsigned)b * (N_ * C4)
                           + (unsigned)(z * NSUB + ty) * C4 + c4;
    const unsigned tstride = (unsigned)(B_ * N_ * C4);
    const int jcnt = (ty < 4) ? JMAX : (JMAX - 1);   // uniform per warp

    const int tid   = ty * 32 + tx;
    const int group = b * 4 + cblk;                  // 0..127
    float4* gp = &g_part[((unsigned)z * NGROUP + (unsigned)group) * (T_ * 32)];

    for (int t = 0; t < T_; ++t) {
        const unsigned tb = (unsigned)t * tstride + bbase;
        float4 part = make_float4(0.f, 0.f, 0.f, 0.f);
#pragma unroll
        for (int j = 0; j < JMAX; ++j) {
            if (j < jcnt) {
                const unsigned idx = tb + (unsigned)(j * (NLANES * C4));
                const float4 xv = x[idx];
                float4 vv;
                vv.x = fmaf(d, v[j].x, xv.x);
                vv.y = fmaf(d, v[j].y, xv.y);
                vv.z = fmaf(d, v[j].z, xv.z);
                vv.w = fmaf(d, v[j].w, xv.w);
                part.x += vv.x; part.y += vv.y;
                part.z += vv.z; part.w += vv.w;
                const bool fx = (vv.x >= 1.0f);
                const bool fy = (vv.y >= 1.0f);
                const bool fz = (vv.z >= 1.0f);
                const bool fw = (vv.w >= 1.0f);
                float4 s;
                s.x = fx ? 1.0f : 0.0f;
                s.y = fy ? 1.0f : 0.0f;
                s.z = fz ? 1.0f : 0.0f;
                s.w = fw ? 1.0f : 0.0f;
                spikes[idx] = s;
                v[j].x = fx ? 0.0f : vv.x;        // hard reset
                v[j].y = fy ? 0.0f : vv.y;
                v[j].z = fz ? 0.0f : vv.z;
                v[j].w = fw ? 0.0f : vv.w;
            }
        }
        red[ty][t & 3][tx] = part;

        if ((t & 3) == 3) {                       // flush 4-timestep window
            __syncthreads();
            if (tid < 128) {                      // 4 t-slots x 32 lanes
                const int tloc = tid >> 5;        // 0..3
                const int cc   = tid & 31;
                float4 sum = red[0][tloc][cc];
#pragma unroll
                for (int k = 1; k < NLANES; ++k) {
                    sum.x += red[k][tloc][cc].x;
                    sum.y += red[k][tloc][cc].y;
                    sum.z += red[k][tloc][cc].z;
                    sum.w += red[k][tloc][cc].w;
                }
                gp[(unsigned)(t - 3 + tloc) * 32u + (unsigned)cc] = sum;
            }
            __syncthreads();
        }
    }

    __threadfence();
    if (tid == 0) {
        const unsigned old = atomicAdd(&g_ctr[group], 1u);
        s_last = ((old % NH) == (NH - 1)) ? 1 : 0;
    }
    __syncthreads();

    if (s_last) {
        __threadfence();   // acquire: see all chunks' scratch writes
#pragma unroll
        for (int o = 0; o < 2; ++o) {
            const int oi = tid + o * 256;         // 0..511 = t*32+cc
            const int t  = oi >> 5;
            const int cc = oi & 31;
            float4 sum = make_float4(0.f, 0.f, 0.f, 0.f);
#pragma unroll
            for (int zz = 0; zz < NH; ++zz) {
                const float4 p =
                    g_part[((unsigned)zz * NGROUP + (unsigned)group) * (T_ * 32)
                           + (unsigned)oi];
                sum.x += p.x; sum.y += p.y; sum.z += p.z; sum.w += p.w;
            }
            const float inv = 1.0f / (float)N_;
            float4 r;
            r.x = sum.x * inv; r.y = sum.y * inv;
            r.z = sum.z * inv; r.w = sum.w * inv;
            vpool[(unsigned)t * (B_ * C4) + (unsigned)b * C4
                  + (unsigned)cblk * 32u + (unsigned)cc] = r;
        }
    }
}

extern "C" void kernel_launch(void* const* d_in, const int* in_sizes, int n_in,
                              void* d_out, int out_size) {
    const float4* x    = (const float4*)d_in[0];
    const float* decay = (const float*)d_in[1];
    float* out = (float*)d_out;

    dim3 block(32, NLANES);             // 256 threads
    dim3 grid(C4 / 32, B_, NH);         // 4 x 32 x 7 = 896 blocks
    lif_dual_kernel<<<grid, block>>>(x, decay, out);
}